// round 13
// baseline (speedup 1.0000x reference)
#include <cuda_runtime.h>
#include <math.h>
#include <stdint.h>

#define B_ 1024
#define T_ 128
#define F_ 32
#define E_ 16
#define H_ 20
#define G_ 80      // 4*H
#define D_ 4096    // T*F
#define BT_ (B_ * T_)   // 131072

// scratch (__device__ globals; no allocations allowed)
__device__ float g_fc1[B_ * D_];                 // relu(x_flat @ fc1_w + b)
__device__ float g_zx[(size_t)E_ * BT_ * G_];    // tensor-computed L1 input proj (+b1)
__device__ float g_eo[E_ * B_];                  // per-expert outputs

// ---------------- helpers -------------------------------------------------
__device__ __forceinline__ float sigmoidf_(float x) {
    return 1.0f / (1.0f + __expf(-x));
}
__device__ __forceinline__ uint32_t f2tf32(float x) {
    uint32_t r; asm("cvt.rna.tf32.f32 %0, %1;" : "=r"(r) : "f"(x)); return r;
}
// D += A(tf32) * B(tf32), m16n8k8
__device__ __forceinline__ void mma_tf32(float* c, const uint32_t* a, const uint32_t* b) {
    asm("mma.sync.aligned.m16n8k8.row.col.f32.tf32.tf32.f32 "
        "{%0,%1,%2,%3},{%4,%5,%6,%7},{%8,%9},{%0,%1,%2,%3};"
        : "+f"(c[0]), "+f"(c[1]), "+f"(c[2]), "+f"(c[3])
        : "r"(a[0]), "r"(a[1]), "r"(a[2]), "r"(a[3]), "r"(b[0]), "r"(b[1]));
}

// ===========================================================================
// kZX: zx[e, r, :] = (BN(x_r) @ k1[e]) + b1[e]   via tf32 tensor MMA (3-pass)
// ===========================================================================
__global__ void __launch_bounds__(256) kZX(
    const float* __restrict__ x,
    const float* __restrict__ bn_gamma, const float* __restrict__ bn_beta,
    const float* __restrict__ bn_mean,  const float* __restrict__ bn_var,
    const float* __restrict__ k1, const float* __restrict__ b1)
{
    __shared__ uint32_t Ah[64][36], Al[64][36];
    __shared__ uint32_t Bh[32][84], Bl[32][84];
    __shared__ float bns[F_], bnh[F_];

    const int tid = threadIdx.x;
    const int r0 = blockIdx.x * 64;

    if (tid < F_) {
        float scv = bn_gamma[tid] * rsqrtf(bn_var[tid] + 1e-3f);
        bns[tid] = scv;
        bnh[tid] = bn_beta[tid] - bn_mean[tid] * scv;
    }
    __syncthreads();

    {
        const int a_row = tid >> 2;
        const int a_kc  = (tid & 3) * 8;
        #pragma unroll
        for (int j = 0; j < 2; j++) {
            const int col = a_kc + j * 4;
            float4 xv = *(const float4*)(x + (size_t)(r0 + a_row) * F_ + col);
            float vf[4] = {xv.x * bns[col] + bnh[col],
                           xv.y * bns[col + 1] + bnh[col + 1],
                           xv.z * bns[col + 2] + bnh[col + 2],
                           xv.w * bns[col + 3] + bnh[col + 3]};
            #pragma unroll
            for (int q = 0; q < 4; q++) {
                uint32_t hi = f2tf32(vf[q]);
                Ah[a_row][col + q] = hi;
                Al[a_row][col + q] = f2tf32(vf[q] - __uint_as_float(hi));
            }
        }
    }
    __syncthreads();

    const int lane = tid & 31;
    const int wid = tid >> 5;
    const int g  = lane >> 2;
    const int tg = lane & 3;
    const int warp_m = wid & 3;
    const int warp_n = wid >> 2;

    for (int e = 0; e < E_; e++) {
        for (int idx = tid; idx < F_ * G_; idx += 256) {
            const int k = idx / G_;
            const int n = idx - k * G_;
            float v = k1[(e * F_ + k) * G_ + n];
            uint32_t hi = f2tf32(v);
            Bh[k][n] = hi;
            Bl[k][n] = f2tf32(v - __uint_as_float(hi));
        }
        __syncthreads();

        float c[5][4];
        #pragma unroll
        for (int nt = 0; nt < 5; nt++)
            #pragma unroll
            for (int j = 0; j < 4; j++) c[nt][j] = 0.f;

        #pragma unroll
        for (int kk = 0; kk < 32; kk += 8) {
            const int ar = warp_m * 16 + g;
            uint32_t ah[4], al[4];
            ah[0] = Ah[ar][kk + tg];     ah[1] = Ah[ar + 8][kk + tg];
            ah[2] = Ah[ar][kk + tg + 4]; ah[3] = Ah[ar + 8][kk + tg + 4];
            al[0] = Al[ar][kk + tg];     al[1] = Al[ar + 8][kk + tg];
            al[2] = Al[ar][kk + tg + 4]; al[3] = Al[ar + 8][kk + tg + 4];
            #pragma unroll
            for (int nt = 0; nt < 5; nt++) {
                const int bc = warp_n * 40 + nt * 8 + g;
                uint32_t bh[2], bl[2];
                bh[0] = Bh[kk + tg][bc]; bh[1] = Bh[kk + tg + 4][bc];
                bl[0] = Bl[kk + tg][bc]; bl[1] = Bl[kk + tg + 4][bc];
                mma_tf32(c[nt], ah, bh);
                mma_tf32(c[nt], ah, bl);
                mma_tf32(c[nt], al, bh);
            }
        }

        #pragma unroll
        for (int nt = 0; nt < 5; nt++) {
            const int row = r0 + warp_m * 16 + g;
            const int col = warp_n * 40 + nt * 8 + 2 * tg;
            float2 bb = *(const float2*)&b1[e * G_ + col];
            float2 o0, o1;
            o0.x = c[nt][0] + bb.x;  o0.y = c[nt][1] + bb.y;
            o1.x = c[nt][2] + bb.x;  o1.y = c[nt][3] + bb.y;
            *(float2*)&g_zx[((size_t)e * BT_ + row) * G_ + col]     = o0;
            *(float2*)&g_zx[((size_t)e * BT_ + row + 8) * G_ + col] = o1;
        }
        __syncthreads();
    }
}

// ===========================================================================
// kFat: 480 threads/block, launch_bounds(480,2) -> 960 thr/SM.
//   blocks [0,1024): fc1 tf32 GEMM, 64x64 tiles
//   blocks [1024,2048): LSTM recurrence, 3-way specialized threads
// ===========================================================================
#define FC1_BLOCKS 1024
#define LROWS 16
#define LSTM_BLOCKS (E_ * B_ / LROWS)   // 1024
#define NT_ 480

struct SFC {                        // fc1 tile buffers (~19.5 KB)
    uint32_t Ah[64][20];
    uint32_t Al[64][20];
    uint32_t Bh[16][72];
    uint32_t Bl[16][72];
};
struct SPL {                        // lstm buffers (~23.5 KB)
    float h1[LROWS][24];            // [0..19] live
    float h2[LROWS][24];
    float z1[LROWS][G_];
    float z2a[LROWS][G_];
    float z2b[LROWS][G_];
    float zxb[LROWS][G_];           // staged zx(t)
};
union __align__(16) UA { SFC f; SPL p; };

__global__ void __launch_bounds__(NT_, 2) kFat(
    const float* __restrict__ x, const float* __restrict__ fc1_w,
    const float* __restrict__ fc1_b,
    const float* __restrict__ r1,
    const float* __restrict__ k2, const float* __restrict__ r2,
    const float* __restrict__ b2,
    const float* __restrict__ dw, const float* __restrict__ db)
{
    __shared__ UA u;
    const int tid = threadIdx.x;

    if (blockIdx.x < FC1_BLOCKS) {
        // ======== fc1: 64x64 block tile, tf32 hi/lo 3-pass ==================
        const int m0 = (blockIdx.x >> 6) * 64;
        const int n0 = (blockIdx.x & 63) * 64;
        const int lane = tid & 31;
        const int wid = tid >> 5;            // 0..14; warps 8..14 idle in MMA
        const int g  = lane >> 2;
        const int tg = lane & 3;
        const int warp_m = wid & 3;          // 4 warps in M (16 rows each)
        const int warp_n = (wid >> 2) & 1;   // 2 warps in N (32 cols each)

        const bool act_a = tid < 256;
        const int a_row = tid >> 2;          // 0..63
        const int a_kc  = (tid & 3) * 4;     // 0,4,8,12
        const bool act_b = (tid >= 224);
        const int bi    = tid - 224;         // 0..255
        const int b_k   = bi >> 4;           // 0..15
        const int b_nc  = (bi & 15) * 4;     // 0..60

        const float* Ap = x + (size_t)(m0 + a_row) * D_ + a_kc;
        const float* Bp = fc1_w + (size_t)b_k * D_ + n0 + b_nc;

        float4 av = make_float4(0,0,0,0), bv = av;
        if (act_a) av = *(const float4*)Ap;
        if (act_b) bv = *(const float4*)Bp;

        float c[4][4];
        #pragma unroll
        for (int nt = 0; nt < 4; nt++)
            #pragma unroll
            for (int j = 0; j < 4; j++) c[nt][j] = 0.f;

        const int NS = D_ / 16;   // 256
        for (int s = 0; s < NS; s++) {
            if (act_a) {
                float af[4] = {av.x, av.y, av.z, av.w};
                #pragma unroll
                for (int j = 0; j < 4; j++) {
                    uint32_t hi = f2tf32(af[j]);
                    u.f.Ah[a_row][a_kc + j] = hi;
                    u.f.Al[a_row][a_kc + j] = f2tf32(af[j] - __uint_as_float(hi));
                }
            }
            if (act_b) {
                float bf[4] = {bv.x, bv.y, bv.z, bv.w};
                #pragma unroll
                for (int j = 0; j < 4; j++) {
                    uint32_t hi = f2tf32(bf[j]);
                    u.f.Bh[b_k][b_nc + j] = hi;
                    u.f.Bl[b_k][b_nc + j] = f2tf32(bf[j] - __uint_as_float(hi));
                }
            }
            __syncthreads();
            if (s + 1 < NS) {
                if (act_a) av = *(const float4*)(Ap + (size_t)(s + 1) * 16);
                if (act_b) bv = *(const float4*)(Bp + (size_t)(s + 1) * 16 * D_);
            }
            if (wid < 8) {
                #pragma unroll
                for (int kk = 0; kk < 16; kk += 8) {
                    const int ar = warp_m * 16 + g;
                    uint32_t ah[4], al[4];
                    ah[0] = u.f.Ah[ar][kk + tg];     ah[1] = u.f.Ah[ar + 8][kk + tg];
                    ah[2] = u.f.Ah[ar][kk + tg + 4]; ah[3] = u.f.Ah[ar + 8][kk + tg + 4];
                    al[0] = u.f.Al[ar][kk + tg];     al[1] = u.f.Al[ar + 8][kk + tg];
                    al[2] = u.f.Al[ar][kk + tg + 4]; al[3] = u.f.Al[ar + 8][kk + tg + 4];
                    #pragma unroll
                    for (int nt = 0; nt < 4; nt++) {
                        const int bc = warp_n * 32 + nt * 8 + g;
                        uint32_t bh[2], bl[2];
                        bh[0] = u.f.Bh[kk + tg][bc]; bh[1] = u.f.Bh[kk + tg + 4][bc];
                        bl[0] = u.f.Bl[kk + tg][bc]; bl[1] = u.f.Bl[kk + tg + 4][bc];
                        mma_tf32(c[nt], ah, bh);
                        mma_tf32(c[nt], ah, bl);
                        mma_tf32(c[nt], al, bh);
                    }
                }
            }
            __syncthreads();
        }

        if (wid < 8) {
            #pragma unroll
            for (int nt = 0; nt < 4; nt++) {
                const int row = m0 + warp_m * 16 + g;
                const int col = n0 + warp_n * 32 + nt * 8 + 2 * tg;
                float2 bb = *(const float2*)&fc1_b[col];
                float2 o0, o1;
                o0.x = fmaxf(c[nt][0] + bb.x, 0.f);
                o0.y = fmaxf(c[nt][1] + bb.y, 0.f);
                o1.x = fmaxf(c[nt][2] + bb.x, 0.f);
                o1.y = fmaxf(c[nt][3] + bb.y, 0.f);
                *(float2*)&g_fc1[(size_t)row * D_ + col]       = o0;
                *(float2*)&g_fc1[(size_t)(row + 8) * D_ + col] = o1;
            }
        }
        return;
    }

    // ======== LSTM recurrence: 3-way specialized, 16 rows/block =============
    const int lb = blockIdx.x - FC1_BLOCKS;
    const int e = lb >> 6;                 // 64 blocks per expert
    const int row0 = (lb & 63) * LROWS;

    const int role = tid / 160;            // 0: z1, 1: z2a(h1@Wk2), 2: z2b(h2@Wr2)
    const int v = tid - role * 160;        // 0..159
    const int rp = v / 80;                 // 0..1 -> rows 8rp..8rp+7
    const int g = v - rp * 80;             // gate column 0..79

    // cells: L1 cells owned by tid<320 (1 each), L2 cells by tid>=160 (1 each)
    const int crow = (tid < 320) ? tid / H_ : 0;
    const int cu   = (tid < 320) ? tid - crow * H_ : 0;
    const int ct   = tid - 160;
    const int crow2 = (tid >= 160) ? ct / H_ : 0;
    const int cu2   = (tid >= 160) ? ct - crow2 * H_ : 0;
    const int sc4  = cu * 4;               // staging float4 col (tid<320)

    // per-role weight column (20 scalars)
    float w[H_];
    float bias2 = 0.f;
    if (role == 0) {
        #pragma unroll
        for (int j = 0; j < H_; j++) w[j] = r1[(e * H_ + j) * G_ + g];
    } else if (role == 1) {
        #pragma unroll
        for (int j = 0; j < H_; j++) w[j] = k2[(e * H_ + j) * G_ + g];
    } else {
        #pragma unroll
        for (int j = 0; j < H_; j++) w[j] = r2[(e * H_ + j) * G_ + g];
        bias2 = b2[e * G_ + g];
    }

    for (int idx = tid; idx < 2 * LROWS * 24; idx += NT_)
        ((float*)u.p.h1)[idx] = 0.f;       // zero h1+h2 (contiguous)

    const float* pzx = g_zx + ((size_t)e * BT_ + (size_t)(row0 + crow) * T_) * G_ + sc4;
    float4 zv = make_float4(0,0,0,0);
    if (tid < 320) {
        *(float4*)&u.p.zxb[crow][sc4] = *(const float4*)pzx;       // zx(0)
        zv = *(const float4*)(pzx + G_);                            // prefetch zx(1)
    }
    __syncthreads();

    float c1 = 0.f, c2 = 0.f;

    for (int t = 0; t <= T_; t++) {
        // ---- phase A: specialized partial dot products (8 rows each) -------
        if (role == 0) {
            if (t < T_) {                   // z1(t) = zx(t) + h1(t-1)@Wr1
                #pragma unroll
                for (int i = 0; i < 8; i++) {
                    const int row = 8 * rp + i;
                    const float4* hp = (const float4*)u.p.h1[row];
                    float4 ha = hp[0], hb = hp[1], hc = hp[2], hd = hp[3], he = hp[4];
                    float a0 = u.p.zxb[row][g], a1 = 0.f, a2 = 0.f, a3 = 0.f;
                    a0 += ha.x * w[0];  a1 += ha.y * w[1];  a2 += ha.z * w[2];  a3 += ha.w * w[3];
                    a0 += hb.x * w[4];  a1 += hb.y * w[5];  a2 += hb.z * w[6];  a3 += hb.w * w[7];
                    a0 += hc.x * w[8];  a1 += hc.y * w[9];  a2 += hc.z * w[10]; a3 += hc.w * w[11];
                    a0 += hd.x * w[12]; a1 += hd.y * w[13]; a2 += hd.z * w[14]; a3 += hd.w * w[15];
                    a0 += he.x * w[16]; a1 += he.y * w[17]; a2 += he.z * w[18]; a3 += he.w * w[19];
                    u.p.z1[row][g] = (a0 + a1) + (a2 + a3);
                }
            }
        } else if (role == 1) {
            if (t >= 1) {                   // z2a(t-1) = h1(t-1)@Wk2
                #pragma unroll
                for (int i = 0; i < 8; i++) {
                    const int row = 8 * rp + i;
                    const float4* hp = (const float4*)u.p.h1[row];
                    float4 ha = hp[0], hb = hp[1], hc = hp[2], hd = hp[3], he = hp[4];
                    float a0 = 0.f, a1 = 0.f, a2 = 0.f, a3 = 0.f;
                    a0 += ha.x * w[0];  a1 += ha.y * w[1];  a2 += ha.z * w[2];  a3 += ha.w * w[3];
                    a0 += hb.x * w[4];  a1 += hb.y * w[5];  a2 += hb.z * w[6];  a3 += hb.w * w[7];
                    a0 += hc.x * w[8];  a1 += hc.y * w[9];  a2 += hc.z * w[10]; a3 += hc.w * w[11];
                    a0 += hd.x * w[12]; a1 += hd.y * w[13]; a2 += hd.z * w[14]; a3 += hd.w * w[15];
                    a0 += he.x * w[16]; a1 += he.y * w[17]; a2 += he.z * w[18]; a3 += he.w * w[19];
                    u.p.z2a[row][g] = (a0 + a1) + (a2 + a3);
                }
            }
        } else {
            if (t >= 1) {                   // z2b(t-1) = b2 + h2(t-2)@Wr2
                #pragma unroll
                for (int i = 0; i < 8; i++) {
                    const int row = 8 * rp + i;
                    const float4* hp = (const float4*)u.p.h2[row];
                    float4 ha = hp[0], hb = hp[1], hc = hp[2], hd = hp[3], he = hp[4];
                    float a0 = bias2, a1 = 0.f, a2 = 0.f, a3 = 0.f;
                    a0 += ha.x * w[0];  a1 += ha.y * w[1];  a2 += ha.z * w[2];  a3 += ha.w * w[3];
                    a0 += hb.x * w[4];  a1 += hb.y * w[5];  a2 += hb.z * w[6];  a3 += hb.w * w[7];
                    a0 += hc.x * w[8];  a1 += hc.y * w[9];  a2 += hc.z * w[10]; a3 += hc.w * w[11];
                    a0 += hd.x * w[12]; a1 += hd.y * w[13]; a2 += hd.z * w[14]; a3 += hd.w * w[15];
                    a0 += he.x * w[16]; a1 += he.y * w[17]; a2 += he.z * w[18]; a3 += he.w * w[19];
                    u.p.z2b[row][g] = (a0 + a1) + (a2 + a3);
                }
            }
        }
        __syncthreads();

        // ---- phase B: cells + staging ---------------------------------------
        if (tid < 320 && t < T_) {          // L1 cell
            float zi = u.p.z1[crow][cu];
            float zf = u.p.z1[crow][H_ + cu];
            float zg = u.p.z1[crow][2 * H_ + cu];
            float zo = u.p.z1[crow][3 * H_ + cu];
            c1 = sigmoidf_(zf) * c1 + sigmoidf_(zi) * fmaxf(zg, 0.f);
            u.p.h1[crow][cu] = sigmoidf_(zo) * fmaxf(c1, 0.f);
        }
        if (tid >= 160 && t >= 1) {         // L2 cell (z2 = z2a + z2b)
            float zi = u.p.z2a[crow2][cu2]           + u.p.z2b[crow2][cu2];
            float zf = u.p.z2a[crow2][H_ + cu2]      + u.p.z2b[crow2][H_ + cu2];
            float zg = u.p.z2a[crow2][2 * H_ + cu2]  + u.p.z2b[crow2][2 * H_ + cu2];
            float zo = u.p.z2a[crow2][3 * H_ + cu2]  + u.p.z2b[crow2][3 * H_ + cu2];
            c2 = sigmoidf_(zf) * c2 + sigmoidf_(zi) * fmaxf(zg, 0.f);
            u.p.h2[crow2][cu2] = sigmoidf_(zo) * fmaxf(c2, 0.f);
        }
        if (tid < 320 && t + 1 < T_) {      // stage zx(t+1), prefetch zx(t+2)
            *(float4*)&u.p.zxb[crow][sc4] = zv;
            const int tn = (t + 2 < T_) ? t + 2 : T_ - 1;
            zv = *(const float4*)(pzx + (size_t)tn * G_);
        }
        __syncthreads();
    }

    // dense head: eo[e,b] = h2(T-1) @ dw[e] + db[e]
    if (tid < LROWS) {
        float acc = db[e];
        #pragma unroll
        for (int j = 0; j < H_; j++) acc += u.p.h2[tid][j] * dw[e * H_ + j];
        g_eo[e * B_ + row0 + tid] = acc;
    }
}

// ===========================================================================
// kC: gate (fc1 row @ gate_w, softmax) + combine -> out[b]
// ===========================================================================
__global__ void __launch_bounds__(320) kC_gate_combine(
    const float* __restrict__ GW, const float* __restrict__ GB,
    float* __restrict__ out)
{
    __shared__ float red[10][E_];
    __shared__ float sv[E_];
    __shared__ float ev[E_];
    __shared__ float part[E_];

    const int b = blockIdx.x;
    const int tid = threadIdx.x;
    float acc[E_];
    #pragma unroll
    for (int e = 0; e < E_; e++) acc[e] = 0.f;

    const float* grow = g_fc1 + (size_t)b * D_;
    for (int k = tid; k < D_; k += 320) {
        float gv = grow[k];
        const float4* wp = (const float4*)(GW + (size_t)k * E_);
        float4 w0 = wp[0], w1 = wp[1], w2 = wp[2], w3 = wp[3];
        acc[0]  += gv * w0.x;  acc[1]  += gv * w0.y;
        acc[2]  += gv * w0.z;  acc[3]  += gv * w0.w;
        acc[4]  += gv * w1.x;  acc[5]  += gv * w1.y;
        acc[6]  += gv * w1.z;  acc[7]  += gv * w1.w;
        acc[8]  += gv * w2.x;  acc[9]  += gv * w2.y;
        acc[10] += gv * w2.z;  acc[11] += gv * w2.w;
        acc[12] += gv * w3.x;  acc[13] += gv * w3.y;
        acc[14] += gv * w3.z;  acc[15] += gv * w3.w;
    }
    #pragma unroll
    for (int e = 0; e < E_; e++) {
        #pragma unroll
        for (int off = 16; off > 0; off >>= 1)
            acc[e] += __shfl_down_sync(0xffffffffu, acc[e], off);
    }
    const int warp = tid >> 5, lane = tid & 31;
    if (lane == 0) {
        #pragma unroll
        for (int e = 0; e < E_; e++) red[warp][e] = acc[e];
    }
    __syncthreads();
    if (tid < E_) {
        float s = GB[tid];
        #pragma unroll
        for (int w = 0; w < 10; w++) s += red[w][tid];
        sv[tid] = s;
    }
    __syncthreads();
    if (tid < E_) {
        float m = sv[0];
        #pragma unroll
        for (int e = 1; e < E_; e++) m = fmaxf(m, sv[e]);
        ev[tid] = expf(sv[tid] - m);
    }
    __syncthreads();
    if (tid < E_) {
        float s = 0.f;
        #pragma unroll
        for (int e = 0; e < E_; e++) s += ev[e];
        part[tid] = (ev[tid] / s) * g_eo[tid * B_ + b];
    }
    __syncthreads();
    if (tid == 0) {
        float s = 0.f;
        #pragma unroll
        for (int e = 0; e < E_; e++) s += part[e];
        out[b] = s;
    }
}

// ---------------------------------------------------------------------------
extern "C" void kernel_launch(void* const* d_in, const int* in_sizes, int n_in,
                              void* d_out, int out_size)
{
    const float* x        = (const float*)d_in[0];
    const float* bn_gamma = (const float*)d_in[1];
    const float* bn_beta  = (const float*)d_in[2];
    const float* bn_mean  = (const float*)d_in[3];
    const float* bn_var   = (const float*)d_in[4];
    const float* k1       = (const float*)d_in[5];
    const float* r1       = (const float*)d_in[6];
    const float* b1       = (const float*)d_in[7];
    const float* k2       = (const float*)d_in[8];
    const float* r2       = (const float*)d_in[9];
    const float* b2       = (const float*)d_in[10];
    const float* dw       = (const float*)d_in[11];
    const float* db       = (const float*)d_in[12];
    const float* fc1_w    = (const float*)d_in[13];
    const float* fc1_b    = (const float*)d_in[14];
    const float* gate_w   = (const float*)d_in[15];
    const float* gate_b   = (const float*)d_in[16];
    float* out = (float*)d_out;

    kZX<<<BT_ / 64, 256>>>(x, bn_gamma, bn_beta, bn_mean, bn_var, k1, b1);

    kFat<<<FC1_BLOCKS + LSTM_BLOCKS, NT_>>>(
        x, fc1_w, fc1_b, r1, k2, r2, b2, dw, db);

    kC_gate_combine<<<B_, 320>>>(gate_w, gate_b, out);
}